// round 9
// baseline (speedup 1.0000x reference)
#include <cuda_runtime.h>

#define B_    128
#define T_    4096
#define FEAT_ 64
#define HID_  24
#define G3_   72            // 3 * HID
#define SPT   4             // steps per tick
#define NTB   (T_ / SPT)    // 1024 compute ticks for warp 0
#define NTICK (NTB + 3)     // + pipeline drain

// Scratch for precomputed GRU1 input gates: [B, T, 72]  (~151 MB)
__device__ float g_xg1[(size_t)B_ * T_ * G3_];

// ---------------------------------------------------------------------------
// Packed f32x2 helpers (PTX 8.6, sm_100+)
// ---------------------------------------------------------------------------
#define FMA2(acc, a, b) \
    asm("fma.rn.f32x2 %0, %1, %2, %0;" : "+l"(acc) : "l"(a), "l"(b))
#define ADD2(d, a, b) \
    asm("add.rn.f32x2 %0, %1, %2;" : "=l"(d) : "l"(a), "l"(b))

__device__ __forceinline__ unsigned long long pk2(float lo, float hi) {
    unsigned long long r;
    asm("mov.b64 %0, {%1, %2};" : "=l"(r) : "f"(lo), "f"(hi));
    return r;
}
__device__ __forceinline__ float hsum2(unsigned long long v) {
    float lo, hi;
    asm("mov.b64 {%0, %1}, %2;" : "=f"(lo), "=f"(hi) : "l"(v));
    return lo + hi;
}
__device__ __forceinline__ float fast_sigmoid(float v) {
    return __fdividef(1.f, 1.f + __expf(-v));
}
__device__ __forceinline__ float fast_tanh(float v) {
    return 1.f - __fdividef(2.f, __expf(2.f * v) + 1.f);
}

// ---------------------------------------------------------------------------
// Kernel 1: grouped causal conv (k=3, groups=4) + LayerNorm + xg1 GEMM
// (unchanged from R8 — 4-wide blocked GEMM, f32x2 throughout)
// ---------------------------------------------------------------------------
__global__ void __launch_bounds__(128, 3) pre_kernel(
    const float* __restrict__ x,       // [B, T, 64]
    const float* __restrict__ conv_w,  // [64, 16, 3]
    const float* __restrict__ conv_b,  // [64]
    const float* __restrict__ gamma,   // [64]
    const float* __restrict__ beta,    // [64]
    const float* __restrict__ w_ih1,   // [72, 64]
    const float* __restrict__ b_ih1)   // [72]
{
    extern __shared__ float sm[];
    float* xs  = sm;                 // 130 * 68
    float* cwt = xs + 130 * 68;      // 3072, transposed to [f][k][c]
    float* cb  = cwt + 3072;         // 64
    float* gm  = cb + 64;            // 64
    float* bt  = gm + 64;            // 64
    float* wi  = bt + 64;            // 4608
    float* b1  = wi + 4608;          // 72

    const int b   = blockIdx.y;
    const int t0  = blockIdx.x * 128;
    const int tid = threadIdx.x;

    const float* xb = x + (size_t)b * T_ * FEAT_;
    for (int i = tid; i < 130 * 64; i += 128) {
        int r = i >> 6, f = i & 63;
        int t = t0 - 2 + r;
        xs[r * 68 + f] = (t >= 0) ? xb[(size_t)t * 64 + f] : 0.f;
    }
    for (int i = tid; i < 3072; i += 128) {
        int f = i / 48, r = i % 48, k = r >> 4, c = r & 15;
        cwt[i] = conv_w[f * 48 + c * 3 + k];
    }
    for (int i = tid; i < 4608; i += 128) wi[i] = w_ih1[i];
    if (tid < 64) { cb[tid] = conv_b[tid]; gm[tid] = gamma[tid]; bt[tid] = beta[tid]; }
    if (tid < 72) b1[tid] = b_ih1[tid];
    __syncthreads();

    float y[64];
    #pragma unroll
    for (int g = 0; g < 4; g++) {
        unsigned long long xk2[3][8];
        #pragma unroll
        for (int k = 0; k < 3; k++) {
            const float4* p = (const float4*)&xs[(tid + k) * 68 + g * 16];
            #pragma unroll
            for (int q = 0; q < 4; q++) {
                float4 v = p[q];
                xk2[k][2*q]   = pk2(v.x, v.y);
                xk2[k][2*q+1] = pk2(v.z, v.w);
            }
        }
        #pragma unroll
        for (int fo = 0; fo < 16; fo++) {
            const int f = g * 16 + fo;
            unsigned long long a0 = 0ull, a1 = 0ull;
            const ulonglong2* wp = (const ulonglong2*)&cwt[f * 48];
            #pragma unroll
            for (int k = 0; k < 3; k++) {
                #pragma unroll
                for (int q = 0; q < 4; q++) {
                    ulonglong2 wv = wp[k * 4 + q];
                    FMA2(a0, wv.x, xk2[k][2*q]);
                    FMA2(a1, wv.y, xk2[k][2*q+1]);
                }
            }
            ADD2(a0, a0, a1);
            y[f] = hsum2(a0) + cb[f];
        }
    }

    float s = 0.f, s2 = 0.f;
    #pragma unroll
    for (int f = 0; f < 64; f++) { s += y[f]; s2 = fmaf(y[f], y[f], s2); }
    float mean = s * (1.f / 64.f);
    float var  = s2 * (1.f / 64.f) - mean * mean;
    float rs   = rsqrtf(var + 1e-5f);
    #pragma unroll
    for (int f = 0; f < 64; f++) y[f] = (y[f] - mean) * rs * gm[f] + bt[f];

    unsigned long long y2[32];
    #pragma unroll
    for (int j = 0; j < 32; j++) y2[j] = pk2(y[2*j], y[2*j+1]);

    float* outp = g_xg1 + ((size_t)b * T_ + (t0 + tid)) * G3_;
    for (int o4 = 0; o4 < 18; o4++) {
        const int o = o4 * 4;
        unsigned long long a0 = 0ull, a1 = 0ull, e0 = 0ull, e1 = 0ull;
        unsigned long long c0 = 0ull, c1 = 0ull, d0 = 0ull, d1 = 0ull;
        const ulonglong2* w0 = (const ulonglong2*)&wi[(o + 0) * 64];
        const ulonglong2* w1 = (const ulonglong2*)&wi[(o + 1) * 64];
        const ulonglong2* w2 = (const ulonglong2*)&wi[(o + 2) * 64];
        const ulonglong2* w3 = (const ulonglong2*)&wi[(o + 3) * 64];
        #pragma unroll
        for (int c = 0; c < 16; c++) {
            ulonglong2 v0 = w0[c], v1 = w1[c], v2 = w2[c], v3 = w3[c];
            FMA2(a0, v0.x, y2[2*c]); FMA2(a1, v0.y, y2[2*c+1]);
            FMA2(e0, v1.x, y2[2*c]); FMA2(e1, v1.y, y2[2*c+1]);
            FMA2(c0, v2.x, y2[2*c]); FMA2(d0, v3.x, y2[2*c]);
            FMA2(c1, v2.y, y2[2*c+1]); FMA2(d1, v3.y, y2[2*c+1]);
        }
        ADD2(a0, a0, a1); ADD2(e0, e0, e1); ADD2(c0, c0, c1); ADD2(d0, d0, d1);
        float4 res;
        res.x = hsum2(a0) + b1[o + 0];
        res.y = hsum2(e0) + b1[o + 1];
        res.z = hsum2(c0) + b1[o + 2];
        res.w = hsum2(d0) + b1[o + 3];
        ((float4*)outp)[o4] = res;
    }
}

// ---------------------------------------------------------------------------
// Kernel 2: layer-pipelined GRU stack, FOUR timesteps per tick, one barrier
// per tick. Warp 1 is also the xg1 producer (LDG with 2-tick lead -> STS),
// so warp 0 (longest stage) does pure register/smem compute.
//   warp 0: GRU1  steps 4tau..4tau+3          (ticks [0,1024))
//   warp 1: xg2 gemvs for tick tau-1; xg1 producer for tick tau+1
//   warp 2: GRU2  for tick tau-2
//   warp 3: FC head for tick tau-3
// ---------------------------------------------------------------------------
__device__ __forceinline__ void load_h64(unsigned long long h64[12], const float* buf) {
    const ulonglong2* hp = (const ulonglong2*)buf;
    #pragma unroll
    for (int q = 0; q < 6; q++) { ulonglong2 v = hp[q]; h64[2*q] = v.x; h64[2*q+1] = v.y; }
}
__device__ __forceinline__ void gemv3(float& gr, float& gz, float& gn,
    const unsigned long long* wr, const unsigned long long* wz, const unsigned long long* wn,
    const unsigned long long h64[12], float br, float bz, float bn) {
    unsigned long long ar = pk2(br, 0.f), az = pk2(bz, 0.f), an = pk2(bn, 0.f);
    #pragma unroll
    for (int j = 0; j < 12; j++) {
        FMA2(ar, wr[j], h64[j]); FMA2(az, wz[j], h64[j]); FMA2(an, wn[j], h64[j]);
    }
    gr = hsum2(ar); gz = hsum2(az); gn = hsum2(an);
}

__global__ void __launch_bounds__(128, 1) gru_kernel(
    const float* __restrict__ h1_0, const float* __restrict__ h2_0,
    const float* __restrict__ w_hh1, const float* __restrict__ b_hh1,
    const float* __restrict__ w_ih2, const float* __restrict__ w_hh2,
    const float* __restrict__ b_ih2, const float* __restrict__ b_hh2,
    const float* __restrict__ fc_w,  const float* __restrict__ fc_b,
    float* __restrict__ out_noise, float* __restrict__ out_h1,
    float* __restrict__ out_h2, int write_extra)
{
    __shared__ __align__(16) float h1pub[2][SPT][24];   // [tick parity][step][lane]
    __shared__ __align__(16) float h2pub[2][SPT][24];
    __shared__ __align__(16) float xg2buf[2][SPT][72];
    __shared__ __align__(16) float xgbuf[2][SPT][72];   // xg1 staging, double-buffered

    const int b    = blockIdx.x;
    const int tid  = threadIdx.x;
    const int w    = tid >> 5;
    const int lane = tid & 31;

    // Per-warp register weights, packed as f32x2 pairs over the input dim.
    unsigned long long wr[12], wz[12], wn[12];
    float br = 0.f, bz = 0.f, bn = 0.f;
    {
        const float* W  = (w == 0) ? w_hh1 : (w == 1) ? w_ih2 : (w == 2) ? w_hh2 : fc_w;
        const float* Bv = (w == 0) ? b_hh1 : (w == 1) ? b_ih2 : (w == 2) ? b_hh2 : fc_b;
        if (w < 3) {
            if (lane < 24) {
                const unsigned long long* Wr = (const unsigned long long*)(W + lane * 24);
                const unsigned long long* Wz = (const unsigned long long*)(W + (24 + lane) * 24);
                const unsigned long long* Wn = (const unsigned long long*)(W + (48 + lane) * 24);
                #pragma unroll
                for (int j = 0; j < 12; j++) { wr[j] = Wr[j]; wz[j] = Wz[j]; wn[j] = Wn[j]; }
                br = Bv[lane]; bz = Bv[24 + lane]; bn = Bv[48 + lane];
            }
        } else {
            const unsigned long long* Wf = (const unsigned long long*)(W + lane * 24);
            #pragma unroll
            for (int j = 0; j < 12; j++) wr[j] = Wf[j];
            br = Bv[lane];
        }
    }

    if (tid < 24) {
        h1pub[1][SPT-1][tid] = h1_0[b * 24 + tid];
        h2pub[1][SPT-1][tid] = h2_0[b * 24 + tid];
    }

    const float* xg = g_xg1 + (size_t)b * T_ * G3_;

    // Prologue: fill xgbuf[0] with steps 0..3 (all threads, synchronous LDG->STS)
    for (int i = tid; i < SPT * 72; i += 128)
        ((float*)xgbuf[0])[i] = xg[i];
    // Warp 1 preloads registers for tick 1 (steps 4..7)
    float rx[SPT], rz_[SPT], rn_[SPT];
    if (w == 1 && lane < 24) {
        #pragma unroll
        for (int s = 0; s < SPT; s++) {
            rx[s]  = __ldg(&xg[(size_t)(SPT + s) * 72 + lane]);
            rz_[s] = __ldg(&xg[(size_t)(SPT + s) * 72 + 24 + lane]);
            rn_[s] = __ldg(&xg[(size_t)(SPT + s) * 72 + 48 + lane]);
        }
    }
    __syncthreads();

    for (int tau = 0; tau < NTICK; tau++) {
        const int ws = tau & 1, rs = ws ^ 1;
        if (w == 0) {
            if (tau < NTB && lane < 24) {
                // all 12 xg scalars upfront (latency hides under first gemv)
                float xr[SPT], xz[SPT], xn[SPT];
                #pragma unroll
                for (int s = 0; s < SPT; s++) {
                    xr[s] = xgbuf[ws][s][lane];
                    xz[s] = xgbuf[ws][s][24 + lane];
                    xn[s] = xgbuf[ws][s][48 + lane];
                }
                float hprev = h1pub[rs][SPT-1][lane];
                const float* hsrc = h1pub[rs][SPT-1];
                #pragma unroll
                for (int s = 0; s < SPT; s++) {
                    unsigned long long h64[12];
                    load_h64(h64, hsrc);
                    float gr, gz, gn;
                    gemv3(gr, gz, gn, wr, wz, wn, h64, br, bz, bn);
                    float r = fast_sigmoid(xr[s] + gr);
                    float z = fast_sigmoid(xz[s] + gz);
                    float n = fast_tanh(xn[s] + r * gn);
                    hprev = n + z * (hprev - n);
                    h1pub[ws][s][lane] = hprev;
                    __syncwarp(0x00ffffffu);
                    hsrc = h1pub[ws][s];
                }
            }
        } else if (w == 1) {
            // stage work: xg2 gemvs for tick tau-1
            if (lane < 24 && tau >= 1 && tau <= NTB) {
                #pragma unroll
                for (int s = 0; s < SPT; s++) {
                    unsigned long long h64[12];
                    load_h64(h64, h1pub[rs][s]);
                    float gr, gz, gn;
                    gemv3(gr, gz, gn, wr, wz, wn, h64, br, bz, bn);
                    xg2buf[ws][s][lane]      = gr;
                    xg2buf[ws][s][24 + lane] = gz;
                    xg2buf[ws][s][48 + lane] = gn;
                }
            }
            // producer: publish tick tau+1's xg (regs loaded 2 ticks ago), then
            // issue LDG for tick tau+2
            if (lane < 24 && tau < NTB) {
                #pragma unroll
                for (int s = 0; s < SPT; s++) {
                    xgbuf[rs][s][lane]      = rx[s];
                    xgbuf[rs][s][24 + lane] = rz_[s];
                    xgbuf[rs][s][48 + lane] = rn_[s];
                }
                #pragma unroll
                for (int s = 0; s < SPT; s++) {
                    int st = SPT * tau + 2 * SPT + s;
                    if (st > T_ - 1) st = T_ - 1;
                    rx[s]  = __ldg(&xg[(size_t)st * 72 + lane]);
                    rz_[s] = __ldg(&xg[(size_t)st * 72 + 24 + lane]);
                    rn_[s] = __ldg(&xg[(size_t)st * 72 + 48 + lane]);
                }
            }
        } else if (w == 2) {
            if (tau >= 2 && tau <= NTB + 1 && lane < 24) {
                float xr[SPT], xz[SPT], xn[SPT];
                #pragma unroll
                for (int s = 0; s < SPT; s++) {
                    xr[s] = xg2buf[rs][s][lane];
                    xz[s] = xg2buf[rs][s][24 + lane];
                    xn[s] = xg2buf[rs][s][48 + lane];
                }
                float hprev = h2pub[rs][SPT-1][lane];
                const float* hsrc = h2pub[rs][SPT-1];
                #pragma unroll
                for (int s = 0; s < SPT; s++) {
                    unsigned long long h64[12];
                    load_h64(h64, hsrc);
                    float gr, gz, gn;
                    gemv3(gr, gz, gn, wr, wz, wn, h64, br, bz, bn);
                    float r = fast_sigmoid(xr[s] + gr);
                    float z = fast_sigmoid(xz[s] + gz);
                    float n = fast_tanh(xn[s] + r * gn);
                    hprev = n + z * (hprev - n);
                    h2pub[ws][s][lane] = hprev;
                    __syncwarp(0x00ffffffu);
                    hsrc = h2pub[ws][s];
                }
            }
        } else {
            if (tau >= 3) {
                const size_t t0o = (size_t)b * T_ + SPT * (tau - 3);
                #pragma unroll
                for (int s = 0; s < SPT; s++) {
                    unsigned long long h64[12];
                    load_h64(h64, h2pub[rs][s]);
                    unsigned long long a = pk2(br, 0.f);
                    #pragma unroll
                    for (int j = 0; j < 12; j++) FMA2(a, wr[j], h64[j]);
                    out_noise[(t0o + s) * 32 + lane] = hsum2(a);
                }
            }
        }
        __syncthreads();
    }

    if (write_extra && tid < 24) {
        out_h1[b * 24 + tid] = h1pub[(NTB - 1) & 1][SPT-1][tid];   // h1(4095)
        out_h2[b * 24 + tid] = h2pub[(NTB + 1) & 1][SPT-1][tid];   // h2(4095)
    }
}

// ---------------------------------------------------------------------------
// Kernel 3: confidence = 1/(1+std(noise, ddof=1)) over last dim (32).
// ---------------------------------------------------------------------------
__global__ void __launch_bounds__(256) conf_kernel(
    const float* __restrict__ noise, float* __restrict__ conf)
{
    const size_t row = (size_t)blockIdx.x * 8 + (threadIdx.x >> 5);
    const int lane = threadIdx.x & 31;
    float o = noise[row * 32 + lane];
    float su = o, sq = o * o;
    #pragma unroll
    for (int m = 16; m >= 1; m >>= 1) {
        su += __shfl_xor_sync(0xffffffffu, su, m);
        sq += __shfl_xor_sync(0xffffffffu, sq, m);
    }
    if (lane == 0) {
        float ss = fmaxf(sq - su * su * (1.f / 32.f), 0.f);
        float sd = sqrtf(ss * (1.f / 31.f));   // ddof = 1
        conf[row] = __fdividef(1.f, 1.f + sd);
    }
}

// ---------------------------------------------------------------------------
extern "C" void kernel_launch(void* const* d_in, const int* in_sizes, int n_in,
                              void* d_out, int out_size)
{
    const float* x      = (const float*)d_in[0];
    const float* h1     = (const float*)d_in[1];
    const float* h2     = (const float*)d_in[2];
    const float* conv_w = (const float*)d_in[3];
    const float* conv_b = (const float*)d_in[4];
    const float* gamma  = (const float*)d_in[5];
    const float* beta   = (const float*)d_in[6];
    const float* w_ih1  = (const float*)d_in[7];
    const float* w_hh1  = (const float*)d_in[8];
    const float* b_ih1  = (const float*)d_in[9];
    const float* b_hh1  = (const float*)d_in[10];
    const float* w_ih2  = (const float*)d_in[11];
    const float* w_hh2  = (const float*)d_in[12];
    const float* b_ih2  = (const float*)d_in[13];
    const float* b_hh2  = (const float*)d_in[14];
    const float* fc_w   = (const float*)d_in[15];
    const float* fc_b   = (const float*)d_in[16];

    float* out = (float*)d_out;
    const size_t NOISE = (size_t)B_ * T_ * 32;
    const size_t FULL  = NOISE + 2 * (size_t)B_ * HID_ + (size_t)B_ * T_;
    int extra = ((size_t)out_size >= FULL) ? 1 : 0;
    float* o_h1   = out + NOISE;
    float* o_h2   = o_h1 + B_ * HID_;
    float* o_conf = o_h2 + B_ * HID_;

    const int SMEM = (130 * 68 + 3072 + 64 * 3 + 4608 + 72) * (int)sizeof(float);
    cudaFuncSetAttribute(pre_kernel, cudaFuncAttributeMaxDynamicSharedMemorySize, SMEM);

    pre_kernel<<<dim3(T_ / 128, B_), 128, SMEM>>>(x, conv_w, conv_b, gamma, beta,
                                                  w_ih1, b_ih1);
    gru_kernel<<<B_, 128>>>(h1, h2, w_hh1, b_hh1, w_ih2, w_hh2, b_ih2, b_hh2,
                            fc_w, fc_b, out, o_h1, o_h2, extra);
    if (extra) conf_kernel<<<(B_ * T_) / 8, 256>>>(out, o_conf);
}